// round 11
// baseline (speedup 1.0000x reference)
#include <cuda_runtime.h>
#include <cuda_bf16.h>
#include <math.h>

#define BSZ 2
#define SEQ 2048
#define DMODEL 4096
#define NH 32
#define NKV 8
#define NREP 4
#define HD 128

#define QSTR (NH * HD)
#define KSTR (NKV * HD)
#define MROWS (BSZ * SEQ)

// ---- fp32 scratch ----
__device__ float g_Q[MROWS * QSTR];
__device__ float g_K[MROWS * KSTR];
__device__ float g_V[MROWS * KSTR];

// ---- bf16 split buffers (GEMM inputs) ----
__device__ __nv_bfloat16 g_x_hi[MROWS * DMODEL];
__device__ __nv_bfloat16 g_x_lo[MROWS * DMODEL];
__device__ __nv_bfloat16 g_wq_hi[DMODEL * DMODEL];
__device__ __nv_bfloat16 g_wq_lo[DMODEL * DMODEL];
__device__ __nv_bfloat16 g_wk_hi[DMODEL * KSTR];
__device__ __nv_bfloat16 g_wk_lo[DMODEL * KSTR];
__device__ __nv_bfloat16 g_wv_hi[DMODEL * KSTR];
__device__ __nv_bfloat16 g_wv_lo[DMODEL * KSTR];
__device__ __nv_bfloat16 g_wo_hi[DMODEL * DMODEL];
__device__ __nv_bfloat16 g_wo_lo[DMODEL * DMODEL];
__device__ __nv_bfloat16 g_o_hi[MROWS * DMODEL];
__device__ __nv_bfloat16 g_o_lo[MROWS * DMODEL];

// ---- bf16 split buffers (attention inputs, post-RoPE) ----
__device__ __nv_bfloat16 g_qb_hi[MROWS * QSTR];
__device__ __nv_bfloat16 g_qb_lo[MROWS * QSTR];
__device__ __nv_bfloat16 g_kb_hi[MROWS * KSTR];
__device__ __nv_bfloat16 g_kb_lo[MROWS * KSTR];
__device__ __nv_bfloat16 g_vb_hi[MROWS * KSTR];
__device__ __nv_bfloat16 g_vb_lo[MROWS * KSTR];

// ---------------------------------------------------------------------------
// asm helpers
// ---------------------------------------------------------------------------
__device__ __forceinline__ void cp16(unsigned int dst, const void* src)
{
    asm volatile("cp.async.cg.shared.global [%0], [%1], 16;" :: "r"(dst), "l"(src));
}
__device__ __forceinline__ void cp_commit()
{
    asm volatile("cp.async.commit_group;");
}
__device__ __forceinline__ void cp_wait1()
{
    asm volatile("cp.async.wait_group 1;");
}
__device__ __forceinline__ void cp_wait0()
{
    asm volatile("cp.async.wait_group 0;");
}
__device__ __forceinline__ void ldm_x4(unsigned int* r, unsigned int addr)
{
    asm volatile("ldmatrix.sync.aligned.m8n8.x4.shared.b16 {%0,%1,%2,%3}, [%4];"
                 : "=r"(r[0]), "=r"(r[1]), "=r"(r[2]), "=r"(r[3]) : "r"(addr));
}
__device__ __forceinline__ void ldm_x4t(unsigned int* r, unsigned int addr)
{
    asm volatile("ldmatrix.sync.aligned.m8n8.x4.trans.shared.b16 {%0,%1,%2,%3}, [%4];"
                 : "=r"(r[0]), "=r"(r[1]), "=r"(r[2]), "=r"(r[3]) : "r"(addr));
}
__device__ __forceinline__ void mma16816(float* d, const unsigned int* a,
                                         unsigned int b0, unsigned int b1)
{
    asm volatile(
        "mma.sync.aligned.m16n8k16.row.col.f32.bf16.bf16.f32 "
        "{%0,%1,%2,%3}, {%4,%5,%6,%7}, {%8,%9}, {%0,%1,%2,%3};"
        : "+f"(d[0]), "+f"(d[1]), "+f"(d[2]), "+f"(d[3])
        : "r"(a[0]), "r"(a[1]), "r"(a[2]), "r"(a[3]), "r"(b0), "r"(b1));
}
__device__ __forceinline__ unsigned int pack_bf2(float x, float y)
{
    __nv_bfloat162 t = __floats2bfloat162_rn(x, y);
    return *(unsigned int*)&t;
}

// ---------------------------------------------------------------------------
// fp32 -> (hi, lo) bf16 split. n % 4 == 0.
// ---------------------------------------------------------------------------
__global__ __launch_bounds__(256) void cvt_split(
    const float* __restrict__ in, __nv_bfloat16* __restrict__ hi,
    __nv_bfloat16* __restrict__ lo, int n)
{
    int i = (blockIdx.x * blockDim.x + threadIdx.x) * 4;
    if (i >= n) {
        return;
    }
    float4 v = *(const float4*)(in + i);
    float vv[4];
    vv[0] = v.x; vv[1] = v.y; vv[2] = v.z; vv[3] = v.w;
    unsigned short H[4];
    unsigned short L[4];
#pragma unroll
    for (int c = 0; c < 4; c++) {
        __nv_bfloat16 h = __float2bfloat16(vv[c]);
        __nv_bfloat16 l = __float2bfloat16(vv[c] - __bfloat162float(h));
        H[c] = *(unsigned short*)&h;
        L[c] = *(unsigned short*)&l;
    }
    *(ushort4*)(hi + i) = make_ushort4(H[0], H[1], H[2], H[3]);
    *(ushort4*)(lo + i) = make_ushort4(L[0], L[1], L[2], L[3]);
}

// ---------------------------------------------------------------------------
// Tensor-core GEMM, bf16 3-term split (fp32 accum).
// 128x256 block tile, BK=32, 256 threads (2x4 warps, 64x64 each), 2-stage.
// A row-major [M,K], B row-major [K,N]. M%128==0, N%256==0, K%32==0.
// ---------------------------------------------------------------------------
#define AST 40
#define BST 264
#define AS_BYTES (128 * AST * 2)                   // 10240
#define BS_BYTES (32 * BST * 2)                    // 16896
#define STAGE_BYTES (2 * AS_BYTES + 2 * BS_BYTES)  // 54272
#define GEMM_SMEM (2 * STAGE_BYTES)                // 108544

__device__ __forceinline__ void issue_stage(
    unsigned int s0,
    const __nv_bfloat16* __restrict__ Ahi, const __nv_bfloat16* __restrict__ Alo,
    const __nv_bfloat16* __restrict__ Bhi, const __nv_bfloat16* __restrict__ Blo,
    int K, int N, int bm, int bn, int k0, int tid)
{
#pragma unroll
    for (int u = 0; u < 2; u++) {
        int idx = tid + u * 256;                 // 0..511
        int r  = idx >> 2;
        int kc = (idx & 3) << 3;
        unsigned int d = s0 + (unsigned int)(r * AST + kc) * 2u;
        cp16(d, Ahi + (size_t)(bm + r) * K + k0 + kc);
        cp16(d + AS_BYTES, Alo + (size_t)(bm + r) * K + k0 + kc);
    }
    unsigned int sb = s0 + 2u * AS_BYTES;
#pragma unroll
    for (int u = 0; u < 4; u++) {
        int idx = tid + u * 256;                 // 0..1023
        int r  = idx >> 5;
        int nc = (idx & 31) << 3;
        unsigned int d = sb + (unsigned int)(r * BST + nc) * 2u;
        cp16(d, Bhi + (size_t)(k0 + r) * N + bn + nc);
        cp16(d + BS_BYTES, Blo + (size_t)(k0 + r) * N + bn + nc);
    }
}

__global__ __launch_bounds__(256) void gemm_bf16x3(
    const __nv_bfloat16* __restrict__ Ahi, const __nv_bfloat16* __restrict__ Alo,
    const __nv_bfloat16* __restrict__ Bhi, const __nv_bfloat16* __restrict__ Blo,
    float* __restrict__ C, int M, int N, int K)
{
    extern __shared__ char smraw[];
    const int tid  = threadIdx.x;
    const int warp = tid >> 5;
    const int lane = tid & 31;
    const int wm   = warp >> 2;          // 0..1 (64 rows each)
    const int wn   = warp & 3;           // 0..3 (64 cols each)
    const int bm   = blockIdx.y * 128;
    const int bn   = blockIdx.x * 256;

    unsigned int sbase = (unsigned int)__cvta_generic_to_shared(smraw);

    float acc[4][8][4];
#pragma unroll
    for (int i = 0; i < 4; i++) {
#pragma unroll
        for (int j = 0; j < 8; j++) {
#pragma unroll
            for (int r = 0; r < 4; r++) {
                acc[i][j][r] = 0.0f;
            }
        }
    }

    const int niter = K / 32;
    issue_stage(sbase, Ahi, Alo, Bhi, Blo, K, N, bm, bn, 0, tid);
    cp_commit();

    const int arow  = lane & 15;
    const int acolh = (lane >> 4) << 3;

    for (int it = 0; it < niter; it++) {
        int cur = it & 1;
        if (it + 1 < niter) {
            issue_stage(sbase + (unsigned int)(cur ^ 1) * STAGE_BYTES,
                        Ahi, Alo, Bhi, Blo, K, N, bm, bn, (it + 1) * 32, tid);
            cp_commit();
            cp_wait1();
        } else {
            cp_wait0();
        }
        __syncthreads();

        unsigned int s0 = sbase + (unsigned int)cur * STAGE_BYTES;
        unsigned int sB = s0 + 2u * AS_BYTES;

#pragma unroll
        for (int ks = 0; ks < 2; ks++) {
            int k16 = ks * 16;
            unsigned int a_hi[4][4];
            unsigned int a_lo[4][4];
#pragma unroll
            for (int mi = 0; mi < 4; mi++) {
                unsigned int addr = s0 +
                    (unsigned int)((wm * 64 + mi * 16 + arow) * AST + k16 + acolh) * 2u;
                ldm_x4(a_hi[mi], addr);
                ldm_x4(a_lo[mi], addr + AS_BYTES);
            }
            unsigned int b_hi[4][4];
            unsigned int b_lo[4][4];
#pragma unroll
            for (int nj = 0; nj < 4; nj++) {
                unsigned int addr = sB +
                    (unsigned int)((k16 + arow) * BST + wn * 64 + nj * 16 + acolh) * 2u;
                ldm_x4t(b_hi[nj], addr);
                ldm_x4t(b_lo[nj], addr + BS_BYTES);
            }
            // term 1: hi*hi
#pragma unroll
            for (int mi = 0; mi < 4; mi++) {
#pragma unroll
                for (int nj = 0; nj < 4; nj++) {
                    mma16816(acc[mi][2 * nj],     a_hi[mi], b_hi[nj][0], b_hi[nj][1]);
                    mma16816(acc[mi][2 * nj + 1], a_hi[mi], b_hi[nj][2], b_hi[nj][3]);
                }
            }
            // term 2: hi*lo
#pragma unroll
            for (int mi = 0; mi < 4; mi++) {
#pragma unroll
                for (int nj = 0; nj < 4; nj++) {
                    mma16816(acc[mi][2 * nj],     a_hi[mi], b_lo[nj][0], b_lo[nj][1]);
                    mma16816(acc[mi][2 * nj + 1], a_hi[mi], b_lo[nj][2], b_lo[nj][3]);
                }
            }
            // term 3: lo*hi
#pragma unroll
            for (int mi = 0; mi < 4; mi++) {
#pragma unroll
                for (int nj = 0; nj < 4; nj++) {
                    mma16816(acc[mi][2 * nj],     a_lo[mi], b_hi[nj][0], b_hi[nj][1]);
                    mma16816(acc[mi][2 * nj + 1], a_lo[mi], b_hi[nj][2], b_hi[nj][3]);
                }
            }
        }
        __syncthreads();
    }

    const int r0 = bm + wm * 64;
    const int c0 = bn + wn * 64;
#pragma unroll
    for (int mi = 0; mi < 4; mi++) {
#pragma unroll
        for (int ng = 0; ng < 8; ng++) {
            int row = r0 + mi * 16 + (lane >> 2);
            int col = c0 + ng * 8 + (lane & 3) * 2;
            *(float2*)(C + (size_t)row * N + col) =
                make_float2(acc[mi][ng][0], acc[mi][ng][1]);
            *(float2*)(C + (size_t)(row + 8) * N + col) =
                make_float2(acc[mi][ng][2], acc[mi][ng][3]);
        }
    }
}

// ---------------------------------------------------------------------------
// RoPE + bf16 hi/lo split. Reads fp32, writes rotated (scaled) hi/lo.
// grid = (rows, nheads), block = 64 threads.
// ---------------------------------------------------------------------------
__global__ __launch_bounds__(64) void rope_split(
    const float* __restrict__ x, __nv_bfloat16* __restrict__ hi,
    __nv_bfloat16* __restrict__ lo, int nheads, float scale)
{
    const int pair = threadIdx.x;
    const int h    = blockIdx.y;
    const int row  = blockIdx.x;
    const int s    = row % SEQ;

    double inv_d = exp(-(double)pair * (1.0 / 64.0) * log(10000.0));
    float  inv_f = (float)inv_d;
    float  ang_f = (float)s * inv_f;

    float c  = (float)cos((double)ang_f);
    float sn = (float)sin((double)ang_f);

    size_t off = (size_t)row * (nheads * HD) + h * HD + pair * 2;
    float x0 = x[off];
    float x1 = x[off + 1];
    float r0 = (x0 * c - x1 * sn) * scale;
    float r1 = (x0 * sn + x1 * c) * scale;

    __nv_bfloat16 h0 = __float2bfloat16(r0);
    __nv_bfloat16 h1 = __float2bfloat16(r1);
    hi[off]     = h0;
    hi[off + 1] = h1;
    lo[off]     = __float2bfloat16(r0 - __bfloat162float(h0));
    lo[off + 1] = __float2bfloat16(r1 - __bfloat162float(h1));
}

// ---------------------------------------------------------------------------
// Flash attention (bf16 mma, hi/lo split QK + PV, fp32 softmax).
// Writes O directly as bf16 hi/lo split (input to the wo GEMM).
// ---------------------------------------------------------------------------
#define FST 136
#define FQ_BYTES (64 * FST * 2)
#define FK_BYTES (32 * FST * 2)
#define FSTAGE (4 * FK_BYTES)
#define FA_SMEM (2 * FQ_BYTES + 2 * FSTAGE)

__global__ __launch_bounds__(128) void flash_attn(
    const __nv_bfloat16* __restrict__ Qh, const __nv_bfloat16* __restrict__ Ql,
    const __nv_bfloat16* __restrict__ Kh, const __nv_bfloat16* __restrict__ Kl,
    const __nv_bfloat16* __restrict__ Vh, const __nv_bfloat16* __restrict__ Vl,
    __nv_bfloat16* __restrict__ Ohi, __nv_bfloat16* __restrict__ Olo)
{
    extern __shared__ char smraw[];
    const int tid  = threadIdx.x;
    const int warp = tid >> 5;
    const int lane = tid & 31;
    const int qt   = blockIdx.x;
    const int h    = blockIdx.y;
    const int b    = blockIdx.z;
    const int g    = h >> 2;
    const int q0   = qt * 64;

    unsigned int sbase = (unsigned int)__cvta_generic_to_shared(smraw);
    unsigned int sQ    = sbase;
    unsigned int sKV   = sbase + 2u * FQ_BYTES;

    {
        size_t rowb = (size_t)b * SEQ + q0;
        for (int i = tid; i < 1024; i += 128) {
            int r = i >> 4;
            int c = (i & 15) << 3;
            size_t goff = (rowb + r) * QSTR + h * HD + c;
            unsigned int d = sQ + (unsigned int)(r * FST + c) * 2u;
            cp16(d, Qh + goff);
            cp16(d + FQ_BYTES, Ql + goff);
        }
    }
    const int nkt = 2 * qt + 2;
    {
        size_t rowb = (size_t)b * SEQ;
        for (int i = tid; i < 512; i += 128) {
            int r = i >> 4;
            int c = (i & 15) << 3;
            size_t goff = (rowb + r) * KSTR + g * HD + c;
            unsigned int d = sKV + (unsigned int)(r * FST + c) * 2u;
            cp16(d, Kh + goff);
            cp16(d + FK_BYTES, Kl + goff);
            cp16(d + 2u * FK_BYTES, Vh + goff);
            cp16(d + 3u * FK_BYTES, Vl + goff);
        }
    }
    cp_commit();

    float oacc[16][4];
#pragma unroll
    for (int i = 0; i < 16; i++) {
#pragma unroll
        for (int j = 0; j < 4; j++) {
            oacc[i][j] = 0.0f;
        }
    }
    float sm0 = -INFINITY;
    float sm1 = -INFINITY;
    float sl0 = 0.0f;
    float sl1 = 0.0f;

    const int arow  = lane & 15;
    const int acolh = (lane >> 4) << 3;
    const int brow  = (lane & 7) | ((lane >> 1) & 8);
    const int bcolh = ((lane >> 3) & 1) << 3;

    for (int kt = 0; kt < nkt; kt++) {
        int st = kt & 1;
        if (kt + 1 < nkt) {
            size_t rowb = (size_t)b * SEQ + (kt + 1) * 32;
            unsigned int sN = sKV + (unsigned int)(st ^ 1) * FSTAGE;
            for (int i = tid; i < 512; i += 128) {
                int r = i >> 4;
                int c = (i & 15) << 3;
                size_t goff = (rowb + r) * KSTR + g * HD + c;
                unsigned int d = sN + (unsigned int)(r * FST + c) * 2u;
                cp16(d, Kh + goff);
                cp16(d + FK_BYTES, Kl + goff);
                cp16(d + 2u * FK_BYTES, Vh + goff);
                cp16(d + 3u * FK_BYTES, Vl + goff);
            }
            cp_commit();
            cp_wait1();
        } else {
            cp_wait0();
        }
        __syncthreads();

        unsigned int pK = sKV + (unsigned int)st * FSTAGE;
        unsigned int pV = pK + 2u * FK_BYTES;

        float sacc[4][4];
#pragma unroll
        for (int i = 0; i < 4; i++) {
#pragma unroll
            for (int j = 0; j < 4; j++) {
                sacc[i][j] = 0.0f;
            }
        }
#pragma unroll
        for (int kk = 0; kk < 8; kk++) {
            unsigned int a_hi[4];
            unsigned int a_lo[4];
            unsigned int aaddr = sQ +
                (unsigned int)((warp * 16 + arow) * FST + kk * 16 + acolh) * 2u;
            ldm_x4(a_hi, aaddr);
            ldm_x4(a_lo, aaddr + FQ_BYTES);
#pragma unroll
            for (int ng = 0; ng < 2; ng++) {
                unsigned int b_hi[4];
                unsigned int b_lo[4];
                unsigned int baddr = pK +
                    (unsigned int)((ng * 16 + brow) * FST + kk * 16 + bcolh) * 2u;
                ldm_x4(b_hi, baddr);
                ldm_x4(b_lo, baddr + FK_BYTES);
                mma16816(sacc[2 * ng],     a_hi, b_hi[0], b_hi[1]);
                mma16816(sacc[2 * ng],     a_hi, b_lo[0], b_lo[1]);
                mma16816(sacc[2 * ng],     a_lo, b_hi[0], b_hi[1]);
                mma16816(sacc[2 * ng + 1], a_hi, b_hi[2], b_hi[3]);
                mma16816(sacc[2 * ng + 1], a_hi, b_lo[2], b_lo[3]);
                mma16816(sacc[2 * ng + 1], a_lo, b_hi[2], b_hi[3]);
            }
        }

        int k0 = kt * 32;
        if (kt >= 2 * qt) {
#pragma unroll
            for (int nt = 0; nt < 4; nt++) {
#pragma unroll
                for (int c = 0; c < 4; c++) {
                    int kg = k0 + nt * 8 + ((lane & 3) << 1) + (c & 1);
                    int qg = q0 + warp * 16 + (lane >> 2) + ((c >> 1) << 3);
                    if (kg > qg) {
                        sacc[nt][c] = -INFINITY;
                    }
                }
            }
        }

        float tm0 = -INFINITY;
        float tm1 = -INFINITY;
#pragma unroll
        for (int nt = 0; nt < 4; nt++) {
            tm0 = fmaxf(tm0, fmaxf(sacc[nt][0], sacc[nt][1]));
            tm1 = fmaxf(tm1, fmaxf(sacc[nt][2], sacc[nt][3]));
        }
        tm0 = fmaxf(tm0, __shfl_xor_sync(0xFFFFFFFFu, tm0, 1));
        tm0 = fmaxf(tm0, __shfl_xor_sync(0xFFFFFFFFu, tm0, 2));
        tm1 = fmaxf(tm1, __shfl_xor_sync(0xFFFFFFFFu, tm1, 1));
        tm1 = fmaxf(tm1, __shfl_xor_sync(0xFFFFFFFFu, tm1, 2));

        float mn0 = fmaxf(sm0, tm0);
        float mn1 = fmaxf(sm1, tm1);
        float al0 = expf(sm0 - mn0);
        float al1 = expf(sm1 - mn1);
        sm0 = mn0;
        sm1 = mn1;

        float rs0 = 0.0f;
        float rs1 = 0.0f;
#pragma unroll
        for (int nt = 0; nt < 4; nt++) {
            float p0 = expf(sacc[nt][0] - mn0);
            float p1 = expf(sacc[nt][1] - mn0);
            float p2 = expf(sacc[nt][2] - mn1);
            float p3 = expf(sacc[nt][3] - mn1);
            sacc[nt][0] = p0;
            sacc[nt][1] = p1;
            sacc[nt][2] = p2;
            sacc[nt][3] = p3;
            rs0 += p0 + p1;
            rs1 += p2 + p3;
        }
        rs0 += __shfl_xor_sync(0xFFFFFFFFu, rs0, 1);
        rs0 += __shfl_xor_sync(0xFFFFFFFFu, rs0, 2);
        rs1 += __shfl_xor_sync(0xFFFFFFFFu, rs1, 1);
        rs1 += __shfl_xor_sync(0xFFFFFFFFu, rs1, 2);
        sl0 = sl0 * al0 + rs0;
        sl1 = sl1 * al1 + rs1;

#pragma unroll
        for (int nt = 0; nt < 16; nt++) {
            oacc[nt][0] *= al0;
            oacc[nt][1] *= al0;
            oacc[nt][2] *= al1;
            oacc[nt][3] *= al1;
        }

#pragma unroll
        for (int ks = 0; ks < 2; ks++) {
            int ntA = 2 * ks;
            int ntB = 2 * ks + 1;
            unsigned int ap_hi[4];
            unsigned int ap_lo[4];
            {
                float pa0 = sacc[ntA][0];
                float pa1 = sacc[ntA][1];
                float ha0 = __bfloat162float(__float2bfloat16(pa0));
                float ha1 = __bfloat162float(__float2bfloat16(pa1));
                ap_hi[0] = pack_bf2(ha0, ha1);
                ap_lo[0] = pack_bf2(pa0 - ha0, pa1 - ha1);
                float pb0 = sacc[ntA][2];
                float pb1 = sacc[ntA][3];
                float hb0 = __bfloat162float(__float2bfloat16(pb0));
                float hb1 = __bfloat162float(__float2bfloat16(pb1));
                ap_hi[1] = pack_bf2(hb0, hb1);
                ap_lo[1] = pack_bf2(pb0 - hb0, pb1 - hb1);
                float pc0 = sacc[ntB][0];
                float pc1 = sacc[ntB][1];
                float hc0 = __bfloat162float(__float2bfloat16(pc0));
                float hc1 = __bfloat162float(__float2bfloat16(pc1));
                ap_hi[2] = pack_bf2(hc0, hc1);
                ap_lo[2] = pack_bf2(pc0 - hc0, pc1 - hc1);
                float pd0 = sacc[ntB][2];
                float pd1 = sacc[ntB][3];
                float hd0 = __bfloat162float(__float2bfloat16(pd0));
                float hd1 = __bfloat162float(__float2bfloat16(pd1));
                ap_hi[3] = pack_bf2(hd0, hd1);
                ap_lo[3] = pack_bf2(pd0 - hd0, pd1 - hd1);
            }
#pragma unroll
            for (int nt2 = 0; nt2 < 8; nt2++) {
                unsigned int b_hi[4];
                unsigned int b_lo[4];
                unsigned int baddr = pV +
                    (unsigned int)((ks * 16 + arow) * FST + nt2 * 16 + acolh) * 2u;
                ldm_x4t(b_hi, baddr);
                ldm_x4t(b_lo, baddr + FK_BYTES);
                mma16816(oacc[2 * nt2],     ap_hi, b_hi[0], b_hi[1]);
                mma16816(oacc[2 * nt2],     ap_hi, b_lo[0], b_lo[1]);
                mma16816(oacc[2 * nt2],     ap_lo, b_hi[0], b_hi[1]);
                mma16816(oacc[2 * nt2 + 1], ap_hi, b_hi[2], b_hi[3]);
                mma16816(oacc[2 * nt2 + 1], ap_hi, b_lo[2], b_lo[3]);
                mma16816(oacc[2 * nt2 + 1], ap_lo, b_hi[2], b_hi[3]);
            }
        }
        __syncthreads();
    }

    // ---- epilogue: write bf16 hi/lo split of O ----
    float i0 = 1.0f / sl0;
    float i1 = 1.0f / sl1;
    int rg = q0 + warp * 16 + (lane >> 2);
    size_t orow0 = ((size_t)b * SEQ + rg) * QSTR + h * HD;
    size_t orow1 = orow0 + (size_t)8 * QSTR;
#pragma unroll
    for (int nt = 0; nt < 16; nt++) {
        int col = nt * 8 + ((lane & 3) << 1);
        float v0 = oacc[nt][0] * i0;
        float v1 = oacc[nt][1] * i0;
        float v2 = oacc[nt][2] * i1;
        float v3 = oacc[nt][3] * i1;
        float h0 = __bfloat162float(__float2bfloat16(v0));
        float h1 = __bfloat162float(__float2bfloat16(v1));
        float h2 = __bfloat162float(__float2bfloat16(v2));
        float h3 = __bfloat162float(__float2bfloat16(v3));
        *(unsigned int*)(Ohi + orow0 + col) = pack_bf2(h0, h1);
        *(unsigned int*)(Olo + orow0 + col) = pack_bf2(v0 - h0, v1 - h1);
        *(unsigned int*)(Ohi + orow1 + col) = pack_bf2(h2, h3);
        *(unsigned int*)(Olo + orow1 + col) = pack_bf2(v2 - h2, v3 - h3);
    }
}

// ---------------------------------------------------------------------------
extern "C" void kernel_launch(void* const* d_in, const int* in_sizes, int n_in,
                              void* d_out, int out_size)
{
    const float* x;
    const float* wq;
    const float* wk;
    const float* wv;
    const float* wo;
    if (n_in >= 7 && in_sizes[0] == 1 && in_sizes[1] == 1) {
        if (in_sizes[2] == 16777216) {
            x  = (const float*)d_in[2];
            wq = (const float*)d_in[3];
            wk = (const float*)d_in[4];
            wv = (const float*)d_in[5];
            wo = (const float*)d_in[6];
        } else {
            wk = (const float*)d_in[2];
            wo = (const float*)d_in[3];
            wq = (const float*)d_in[4];
            wv = (const float*)d_in[5];
            x  = (const float*)d_in[6];
        }
    } else {
        x  = (const float*)d_in[0];
        wq = (const float*)d_in[1];
        wk = (const float*)d_in[2];
        wv = (const float*)d_in[3];
        wo = (const float*)d_in[4];
    }
    float* out = (float*)d_out;

    float* Qp;
    float* Kp;
    float* Vp;
    cudaGetSymbolAddress((void**)&Qp, g_Q);
    cudaGetSymbolAddress((void**)&Kp, g_K);
    cudaGetSymbolAddress((void**)&Vp, g_V);

    __nv_bfloat16* xh;
    __nv_bfloat16* xl;
    __nv_bfloat16* qh;
    __nv_bfloat16* ql;
    __nv_bfloat16* kh;
    __nv_bfloat16* kl;
    __nv_bfloat16* vh;
    __nv_bfloat16* vl;
    __nv_bfloat16* oh;
    __nv_bfloat16* ol;
    __nv_bfloat16* ph;
    __nv_bfloat16* pl;
    cudaGetSymbolAddress((void**)&xh, g_x_hi);
    cudaGetSymbolAddress((void**)&xl, g_x_lo);
    cudaGetSymbolAddress((void**)&qh, g_wq_hi);
    cudaGetSymbolAddress((void**)&ql, g_wq_lo);
    cudaGetSymbolAddress((void**)&kh, g_wk_hi);
    cudaGetSymbolAddress((void**)&kl, g_wk_lo);
    cudaGetSymbolAddress((void**)&vh, g_wv_hi);
    cudaGetSymbolAddress((void**)&vl, g_wv_lo);
    cudaGetSymbolAddress((void**)&oh, g_wo_hi);
    cudaGetSymbolAddress((void**)&ol, g_wo_lo);
    cudaGetSymbolAddress((void**)&ph, g_o_hi);
    cudaGetSymbolAddress((void**)&pl, g_o_lo);

    __nv_bfloat16* qbh;
    __nv_bfloat16* qbl;
    __nv_bfloat16* kbh;
    __nv_bfloat16* kbl;
    __nv_bfloat16* vbh;
    __nv_bfloat16* vbl;
    cudaGetSymbolAddress((void**)&qbh, g_qb_hi);
    cudaGetSymbolAddress((void**)&qbl, g_qb_lo);
    cudaGetSymbolAddress((void**)&kbh, g_kb_hi);
    cudaGetSymbolAddress((void**)&kbl, g_kb_lo);
    cudaGetSymbolAddress((void**)&vbh, g_vb_hi);
    cudaGetSymbolAddress((void**)&vbl, g_vb_lo);

    const int M = MROWS;

    const int n1 = M * DMODEL;
    const int n2 = DMODEL * DMODEL;
    const int n3 = DMODEL * KSTR;
    cvt_split<<<n1 / 1024, 256>>>(x,  xh, xl, n1);
    cvt_split<<<n2 / 1024, 256>>>(wq, qh, ql, n2);
    cvt_split<<<n3 / 1024, 256>>>(wk, kh, kl, n3);
    cvt_split<<<n3 / 1024, 256>>>(wv, vh, vl, n3);
    cvt_split<<<n2 / 1024, 256>>>(wo, oh, ol, n2);

    cudaFuncSetAttribute(gemm_bf16x3,
                         cudaFuncAttributeMaxDynamicSharedMemorySize, GEMM_SMEM);
    cudaFuncSetAttribute(flash_attn,
                         cudaFuncAttributeMaxDynamicSharedMemorySize, FA_SMEM);

    gemm_bf16x3<<<dim3(DMODEL / 256, M / 128), 256, GEMM_SMEM>>>(
        xh, xl, qh, ql, Qp, M, DMODEL, DMODEL);
    gemm_bf16x3<<<dim3(KSTR / 256, M / 128), 256, GEMM_SMEM>>>(
        xh, xl, kh, kl, Kp, M, KSTR, DMODEL);
    gemm_bf16x3<<<dim3(KSTR / 256, M / 128), 256, GEMM_SMEM>>>(
        xh, xl, vh, vl, Vp, M, KSTR, DMODEL);

    const float scale = 0.08838834764831845f;
    rope_split<<<dim3(M, NH), 64>>>(Qp, qbh, qbl, NH, scale);
    rope_split<<<dim3(M, NKV), 64>>>(Kp, kbh, kbl, NKV, 1.0f);
    cvt_split<<<(M * KSTR) / 1024, 256>>>(Vp, vbh, vbl, M * KSTR);

    flash_attn<<<dim3(SEQ / 64, NH, BSZ), 128, FA_SMEM>>>(
        qbh, qbl, kbh, kbl, vbh, vbl, ph, pl);

    gemm_bf16x3<<<dim3(DMODEL / 256, M / 128), 256, GEMM_SMEM>>>(
        ph, pl, oh, ol, out, M, DMODEL, DMODEL);
}

// round 14
// speedup vs baseline: 1.7629x; 1.7629x over previous
#include <cuda_runtime.h>
#include <cuda_fp16.h>
#include <math.h>

#define BSZ 2
#define SEQ 2048
#define DMODEL 4096
#define NH 32
#define NKV 8
#define NREP 4
#define HD 128

#define QSTR (NH * HD)
#define KSTR (NKV * HD)
#define MROWS (BSZ * SEQ)

// ---- fp32 scratch (pre-RoPE Q/K, pre-convert V) ----
__device__ float g_Q[MROWS * QSTR];
__device__ float g_K[MROWS * KSTR];
__device__ float g_V[MROWS * KSTR];

// ---- fp16 buffers ----
__device__ __half g_xh[MROWS * DMODEL];
__device__ __half g_wqh[DMODEL * DMODEL];
__device__ __half g_wkh[DMODEL * KSTR];
__device__ __half g_wvh[DMODEL * KSTR];
__device__ __half g_woh[DMODEL * DMODEL];
__device__ __half g_oh[MROWS * DMODEL];       // attention output (fp16)
__device__ __half g_qbh[MROWS * QSTR];        // post-RoPE Q (scaled)
__device__ __half g_kbh[MROWS * KSTR];        // post-RoPE K
__device__ __half g_vbh[MROWS * KSTR];        // V

// ---------------------------------------------------------------------------
// asm helpers
// ---------------------------------------------------------------------------
__device__ __forceinline__ void cp16(unsigned int dst, const void* src)
{
    asm volatile("cp.async.cg.shared.global [%0], [%1], 16;" :: "r"(dst), "l"(src));
}
__device__ __forceinline__ void cp_commit()
{
    asm volatile("cp.async.commit_group;");
}
__device__ __forceinline__ void cp_wait1()
{
    asm volatile("cp.async.wait_group 1;");
}
__device__ __forceinline__ void cp_wait0()
{
    asm volatile("cp.async.wait_group 0;");
}
__device__ __forceinline__ void ldm_x4(unsigned int* r, unsigned int addr)
{
    asm volatile("ldmatrix.sync.aligned.m8n8.x4.shared.b16 {%0,%1,%2,%3}, [%4];"
                 : "=r"(r[0]), "=r"(r[1]), "=r"(r[2]), "=r"(r[3]) : "r"(addr));
}
__device__ __forceinline__ void ldm_x4t(unsigned int* r, unsigned int addr)
{
    asm volatile("ldmatrix.sync.aligned.m8n8.x4.trans.shared.b16 {%0,%1,%2,%3}, [%4];"
                 : "=r"(r[0]), "=r"(r[1]), "=r"(r[2]), "=r"(r[3]) : "r"(addr));
}
__device__ __forceinline__ void mma16816h(float* d, const unsigned int* a,
                                          unsigned int b0, unsigned int b1)
{
    asm volatile(
        "mma.sync.aligned.m16n8k16.row.col.f32.f16.f16.f32 "
        "{%0,%1,%2,%3}, {%4,%5,%6,%7}, {%8,%9}, {%0,%1,%2,%3};"
        : "+f"(d[0]), "+f"(d[1]), "+f"(d[2]), "+f"(d[3])
        : "r"(a[0]), "r"(a[1]), "r"(a[2]), "r"(a[3]), "r"(b0), "r"(b1));
}
__device__ __forceinline__ unsigned int pack_h2(float x, float y)
{
    __half2 t = __floats2half2_rn(x, y);
    return *(unsigned int*)&t;
}

// ---------------------------------------------------------------------------
// fp32 -> fp16. n % 8 == 0.
// ---------------------------------------------------------------------------
__global__ __launch_bounds__(256) void cvt_half(
    const float* __restrict__ in, __half* __restrict__ out, int n)
{
    int i = (blockIdx.x * blockDim.x + threadIdx.x) * 8;
    if (i >= n) {
        return;
    }
    float4 a = *(const float4*)(in + i);
    float4 b = *(const float4*)(in + i + 4);
    unsigned int r0 = pack_h2(a.x, a.y);
    unsigned int r1 = pack_h2(a.z, a.w);
    unsigned int r2 = pack_h2(b.x, b.y);
    unsigned int r3 = pack_h2(b.z, b.w);
    uint4 v;
    v.x = r0;
    v.y = r1;
    v.z = r2;
    v.w = r3;
    *(uint4*)(out + i) = v;
}

// ---------------------------------------------------------------------------
// Tensor-core GEMM, plain fp16, fp32 accum.
// C[M,N] = A[M,K] @ B[K,N]. 128x128 tile, BK=32, 256 threads, 2-stage.
// ---------------------------------------------------------------------------
#define AST 40
#define BST 136
#define AS_BYTES (128 * AST * 2)                 // 10240
#define BS_BYTES (32 * BST * 2)                  // 8704
#define STAGE_BYTES (AS_BYTES + BS_BYTES)        // 18944
#define GEMM_SMEM (2 * STAGE_BYTES)              // 37888

__device__ __forceinline__ void issue_stage(
    unsigned int s0,
    const __half* __restrict__ A, const __half* __restrict__ B,
    int K, int N, int bm, int bn, int k0,
    int ar0, int ar1, int ak, int br0, int br1, int bc)
{
    unsigned int da0 = s0 + (unsigned int)(ar0 * AST + ak) * 2u;
    cp16(da0, A + (size_t)(bm + ar0) * K + k0 + ak);
    unsigned int da1 = s0 + (unsigned int)(ar1 * AST + ak) * 2u;
    cp16(da1, A + (size_t)(bm + ar1) * K + k0 + ak);
    unsigned int db0 = s0 + AS_BYTES + (unsigned int)(br0 * BST + bc) * 2u;
    cp16(db0, B + (size_t)(k0 + br0) * N + bn + bc);
    unsigned int db1 = s0 + AS_BYTES + (unsigned int)(br1 * BST + bc) * 2u;
    cp16(db1, B + (size_t)(k0 + br1) * N + bn + bc);
}

__global__ __launch_bounds__(256) void gemm_f16(
    const __half* __restrict__ A, const __half* __restrict__ B,
    float* __restrict__ C, int M, int N, int K)
{
    extern __shared__ char smraw[];
    const int tid  = threadIdx.x;
    const int warp = tid >> 5;
    const int lane = tid & 31;
    const int wm   = warp >> 2;
    const int wn   = warp & 3;
    const int bm   = blockIdx.y * 128;
    const int bn   = blockIdx.x * 128;

    unsigned int sbase = (unsigned int)__cvta_generic_to_shared(smraw);

    float acc[4][4][4];
#pragma unroll
    for (int i = 0; i < 4; i++) {
#pragma unroll
        for (int j = 0; j < 4; j++) {
#pragma unroll
            for (int r = 0; r < 4; r++) {
                acc[i][j][r] = 0.0f;
            }
        }
    }

    const int ar0 = tid >> 2;
    const int ar1 = (tid + 256) >> 2;
    const int ak  = (tid & 3) << 3;
    const int br0 = tid >> 4;
    const int br1 = (tid + 256) >> 4;
    const int bc  = (tid & 15) << 3;

    const int niter = K / 32;
    issue_stage(sbase, A, B, K, N, bm, bn, 0, ar0, ar1, ak, br0, br1, bc);
    cp_commit();

    const int arow  = lane & 15;
    const int acolh = (lane >> 4) << 3;

    for (int it = 0; it < niter; it++) {
        int cur = it & 1;
        if (it + 1 < niter) {
            issue_stage(sbase + (unsigned int)(cur ^ 1) * STAGE_BYTES,
                        A, B, K, N, bm, bn, (it + 1) * 32,
                        ar0, ar1, ak, br0, br1, bc);
            cp_commit();
            cp_wait1();
        } else {
            cp_wait0();
        }
        __syncthreads();

        unsigned int s0 = sbase + (unsigned int)cur * STAGE_BYTES;
        unsigned int sB = s0 + AS_BYTES;

#pragma unroll
        for (int ks = 0; ks < 2; ks++) {
            int k16 = ks * 16;
            unsigned int af[4][4];
#pragma unroll
            for (int mi = 0; mi < 4; mi++) {
                unsigned int addr = s0 +
                    (unsigned int)((wm * 64 + mi * 16 + arow) * AST + k16 + acolh) * 2u;
                ldm_x4(af[mi], addr);
            }
            unsigned int bf[2][4];
#pragma unroll
            for (int nj = 0; nj < 2; nj++) {
                unsigned int addr = sB +
                    (unsigned int)((k16 + arow) * BST + wn * 32 + nj * 16 + acolh) * 2u;
                ldm_x4t(bf[nj], addr);
            }
#pragma unroll
            for (int mi = 0; mi < 4; mi++) {
#pragma unroll
                for (int nj = 0; nj < 2; nj++) {
                    mma16816h(acc[mi][2 * nj],     af[mi], bf[nj][0], bf[nj][1]);
                    mma16816h(acc[mi][2 * nj + 1], af[mi], bf[nj][2], bf[nj][3]);
                }
            }
        }
        __syncthreads();
    }

    const int r0 = bm + wm * 64;
    const int c0 = bn + wn * 32;
#pragma unroll
    for (int mi = 0; mi < 4; mi++) {
#pragma unroll
        for (int ng = 0; ng < 4; ng++) {
            int row = r0 + mi * 16 + (lane >> 2);
            int col = c0 + ng * 8 + (lane & 3) * 2;
            *(float2*)(C + (size_t)row * N + col) =
                make_float2(acc[mi][ng][0], acc[mi][ng][1]);
            *(float2*)(C + (size_t)(row + 8) * N + col) =
                make_float2(acc[mi][ng][2], acc[mi][ng][3]);
        }
    }
}

// ---------------------------------------------------------------------------
// RoPE -> fp16 (accurate double trig; scale folded). grid=(rows,nheads),64thr.
// ---------------------------------------------------------------------------
__global__ __launch_bounds__(64) void rope_half(
    const float* __restrict__ x, __half* __restrict__ out, int nheads, float scale)
{
    const int pair = threadIdx.x;
    const int h    = blockIdx.y;
    const int row  = blockIdx.x;
    const int s    = row % SEQ;

    double inv_d = exp(-(double)pair * (1.0 / 64.0) * log(10000.0));
    float  inv_f = (float)inv_d;
    float  ang_f = (float)s * inv_f;

    float c  = (float)cos((double)ang_f);
    float sn = (float)sin((double)ang_f);

    size_t off = (size_t)row * (nheads * HD) + h * HD + pair * 2;
    float x0 = x[off];
    float x1 = x[off + 1];
    float r0 = (x0 * c - x1 * sn) * scale;
    float r1 = (x0 * sn + x1 * c) * scale;

    *(unsigned int*)(out + off) = pack_h2(r0, r1);
}

// ---------------------------------------------------------------------------
// Flash attention (fp16 mma, fp32 softmax/accum). Writes fp16 O.
// Block = (64-row q tile, head, batch). 4 warps. K-tiles of 32, 2-stage.
// ---------------------------------------------------------------------------
#define FST 136
#define FQ_BYTES (64 * FST * 2)          // 17408
#define FK_BYTES (32 * FST * 2)          // 8704
#define FSTAGE (2 * FK_BYTES)            // K, V
#define FA_SMEM (FQ_BYTES + 2 * FSTAGE)  // 52224

__global__ __launch_bounds__(128) void flash_f16(
    const __half* __restrict__ Qh, const __half* __restrict__ Kh,
    const __half* __restrict__ Vh, __half* __restrict__ O)
{
    extern __shared__ char smraw[];
    const int tid  = threadIdx.x;
    const int warp = tid >> 5;
    const int lane = tid & 31;
    const int qt   = blockIdx.x;
    const int h    = blockIdx.y;
    const int b    = blockIdx.z;
    const int g    = h >> 2;
    const int q0   = qt * 64;

    unsigned int sbase = (unsigned int)__cvta_generic_to_shared(smraw);
    unsigned int sQ    = sbase;
    unsigned int sKV   = sbase + FQ_BYTES;

    {
        size_t rowb = (size_t)b * SEQ + q0;
        for (int i = tid; i < 1024; i += 128) {
            int r = i >> 4;
            int c = (i & 15) << 3;
            size_t goff = (rowb + r) * QSTR + h * HD + c;
            cp16(sQ + (unsigned int)(r * FST + c) * 2u, Qh + goff);
        }
    }
    const int nkt = 2 * qt + 2;
    {
        size_t rowb = (size_t)b * SEQ;
        for (int i = tid; i < 512; i += 128) {
            int r = i >> 4;
            int c = (i & 15) << 3;
            size_t goff = (rowb + r) * KSTR + g * HD + c;
            unsigned int d = sKV + (unsigned int)(r * FST + c) * 2u;
            cp16(d, Kh + goff);
            cp16(d + FK_BYTES, Vh + goff);
        }
    }
    cp_commit();

    float oacc[16][4];
#pragma unroll
    for (int i = 0; i < 16; i++) {
#pragma unroll
        for (int j = 0; j < 4; j++) {
            oacc[i][j] = 0.0f;
        }
    }
    float sm0 = -INFINITY;
    float sm1 = -INFINITY;
    float sl0 = 0.0f;
    float sl1 = 0.0f;

    const int arow  = lane & 15;
    const int acolh = (lane >> 4) << 3;
    const int brow  = (lane & 7) | ((lane >> 1) & 8);
    const int bcolh = ((lane >> 3) & 1) << 3;

    for (int kt = 0; kt < nkt; kt++) {
        int st = kt & 1;
        if (kt + 1 < nkt) {
            size_t rowb = (size_t)b * SEQ + (kt + 1) * 32;
            unsigned int sN = sKV + (unsigned int)(st ^ 1) * FSTAGE;
            for (int i = tid; i < 512; i += 128) {
                int r = i >> 4;
                int c = (i & 15) << 3;
                size_t goff = (rowb + r) * KSTR + g * HD + c;
                unsigned int d = sN + (unsigned int)(r * FST + c) * 2u;
                cp16(d, Kh + goff);
                cp16(d + FK_BYTES, Vh + goff);
            }
            cp_commit();
            cp_wait1();
        } else {
            cp_wait0();
        }
        __syncthreads();

        unsigned int pK = sKV + (unsigned int)st * FSTAGE;
        unsigned int pV = pK + FK_BYTES;

        float sacc[4][4];
#pragma unroll
        for (int i = 0; i < 4; i++) {
#pragma unroll
            for (int j = 0; j < 4; j++) {
                sacc[i][j] = 0.0f;
            }
        }
#pragma unroll
        for (int kk = 0; kk < 8; kk++) {
            unsigned int af[4];
            unsigned int aaddr = sQ +
                (unsigned int)((warp * 16 + arow) * FST + kk * 16 + acolh) * 2u;
            ldm_x4(af, aaddr);
#pragma unroll
            for (int ng = 0; ng < 2; ng++) {
                unsigned int bf[4];
                unsigned int baddr = pK +
                    (unsigned int)((ng * 16 + brow) * FST + kk * 16 + bcolh) * 2u;
                ldm_x4(bf, baddr);
                mma16816h(sacc[2 * ng],     af, bf[0], bf[1]);
                mma16816h(sacc[2 * ng + 1], af, bf[2], bf[3]);
            }
        }

        int k0 = kt * 32;
        if (kt >= 2 * qt) {
#pragma unroll
            for (int nt = 0; nt < 4; nt++) {
#pragma unroll
                for (int c = 0; c < 4; c++) {
                    int kg = k0 + nt * 8 + ((lane & 3) << 1) + (c & 1);
                    int qg = q0 + warp * 16 + (lane >> 2) + ((c >> 1) << 3);
                    if (kg > qg) {
                        sacc[nt][c] = -INFINITY;
                    }
                }
            }
        }

        float tm0 = -INFINITY;
        float tm1 = -INFINITY;
#pragma unroll
        for (int nt = 0; nt < 4; nt++) {
            tm0 = fmaxf(tm0, fmaxf(sacc[nt][0], sacc[nt][1]));
            tm1 = fmaxf(tm1, fmaxf(sacc[nt][2], sacc[nt][3]));
        }
        tm0 = fmaxf(tm0, __shfl_xor_sync(0xFFFFFFFFu, tm0, 1));
        tm0 = fmaxf(tm0, __shfl_xor_sync(0xFFFFFFFFu, tm0, 2));
        tm1 = fmaxf(tm1, __shfl_xor_sync(0xFFFFFFFFu, tm1, 1));
        tm1 = fmaxf(tm1, __shfl_xor_sync(0xFFFFFFFFu, tm1, 2));

        float mn0 = fmaxf(sm0, tm0);
        float mn1 = fmaxf(sm1, tm1);
        float al0 = expf(sm0 - mn0);
        float al1 = expf(sm1 - mn1);
        sm0 = mn0;
        sm1 = mn1;

        float rs0 = 0.0f;
        float rs1 = 0.0f;
#pragma unroll
        for (int nt = 0; nt < 4; nt++) {
            float p0 = expf(sacc[nt][0] - mn0);
            float p1 = expf(sacc[nt][1] - mn0);
            float p2 = expf(sacc[nt][2] - mn1);
            float p3 = expf(sacc[nt][3] - mn1);
            sacc[nt][0] = p0;
            sacc[nt][1] = p1;
            sacc[nt][2] = p2;
            sacc[nt][3] = p3;
            rs0 += p0 + p1;
            rs1 += p2 + p3;
        }
        rs0 += __shfl_xor_sync(0xFFFFFFFFu, rs0, 1);
        rs0 += __shfl_xor_sync(0xFFFFFFFFu, rs0, 2);
        rs1 += __shfl_xor_sync(0xFFFFFFFFu, rs1, 1);
        rs1 += __shfl_xor_sync(0xFFFFFFFFu, rs1, 2);
        sl0 = sl0 * al0 + rs0;
        sl1 = sl1 * al1 + rs1;

#pragma unroll
        for (int nt = 0; nt < 16; nt++) {
            oacc[nt][0] *= al0;
            oacc[nt][1] *= al0;
            oacc[nt][2] *= al1;
            oacc[nt][3] *= al1;
        }

#pragma unroll
        for (int ks = 0; ks < 2; ks++) {
            int ntA = 2 * ks;
            int ntB = 2 * ks + 1;
            unsigned int ap[4];
            ap[0] = pack_h2(sacc[ntA][0], sacc[ntA][1]);
            ap[1] = pack_h2(sacc[ntA][2], sacc[ntA][3]);
            ap[2] = pack_h2(sacc[ntB][0], sacc[ntB][1]);
            ap[3] = pack_h2(sacc[ntB][2], sacc[ntB][3]);
#pragma unroll
            for (int nt2 = 0; nt2 < 8; nt2++) {
                unsigned int bf[4];
                unsigned int baddr = pV +
                    (unsigned int)((ks * 16 + arow) * FST + nt2 * 16 + acolh) * 2u;
                ldm_x4t(bf, baddr);
                mma16816h(oacc[2 * nt2],     ap, bf[0], bf[1]);
                mma16816h(oacc[2 * nt2 + 1], ap, bf[2], bf[3]);
            }
        }
        __syncthreads();
    }

    float i0 = 1.0f / sl0;
    float i1 = 1.0f / sl1;
    int rg = q0 + warp * 16 + (lane >> 2);
    size_t orow0 = ((size_t)b * SEQ + rg) * QSTR + h * HD;
    size_t orow1 = orow0 + (size_t)8 * QSTR;
#pragma unroll
    for (int nt = 0; nt < 16; nt++) {
        int col = nt * 8 + ((lane & 3) << 1);
        *(unsigned int*)(O + orow0 + col) = pack_h2(oacc[nt][0] * i0, oacc[nt][1] * i0);
        *(unsigned int*)(O + orow1 + col) = pack_h2(oacc[nt][2] * i1, oacc[nt][3] * i1);
    }
}

// ---------------------------------------------------------------------------
extern "C" void kernel_launch(void* const* d_in, const int* in_sizes, int n_in,
                              void* d_out, int out_size)
{
    const float* x;
    const float* wq;
    const float* wk;
    const float* wv;
    const float* wo;
    if (n_in >= 7 && in_sizes[0] == 1 && in_sizes[1] == 1) {
        if (in_sizes[2] == 16777216) {
            x  = (const float*)d_in[2];
            wq = (const float*)d_in[3];
            wk = (const float*)d_in[4];
            wv = (const float*)d_in[5];
            wo = (const float*)d_in[6];
        } else {
            wk = (const float*)d_in[2];
            wo = (const float*)d_in[3];
            wq = (const float*)d_in[4];
            wv = (const float*)d_in[5];
            x  = (const float*)d_in[6];
        }
    } else {
        x  = (const float*)d_in[0];
        wq = (const float*)d_in[1];
        wk = (const float*)d_in[2];
        wv = (const float*)d_in[3];
        wo = (const float*)d_in[4];
    }
    float* out = (float*)d_out;

    float* Qp;
    float* Kp;
    float* Vp;
    cudaGetSymbolAddress((void**)&Qp, g_Q);
    cudaGetSymbolAddress((void**)&Kp, g_K);
    cudaGetSymbolAddress((void**)&Vp, g_V);

    __half* xh;
    __half* wqh;
    __half* wkh;
    __half* wvh;
    __half* woh;
    __half* ohp;
    __half* qbh;
    __half* kbh;
    __half* vbh;
    cudaGetSymbolAddress((void**)&xh,  g_xh);
    cudaGetSymbolAddress((void**)&wqh, g_wqh);
    cudaGetSymbolAddress((void**)&wkh, g_wkh);
    cudaGetSymbolAddress((void**)&wvh, g_wvh);
    cudaGetSymbolAddress((void**)&woh, g_woh);
    cudaGetSymbolAddress((void**)&ohp, g_oh);
    cudaGetSymbolAddress((void**)&qbh, g_qbh);
    cudaGetSymbolAddress((void**)&kbh, g_kbh);
    cudaGetSymbolAddress((void**)&vbh, g_vbh);

    const int M = MROWS;

    // fp32 -> fp16 converts
    cvt_half<<<(M * DMODEL) / 2048, 256>>>(x, xh, M * DMODEL);
    cvt_half<<<(DMODEL * DMODEL) / 2048, 256>>>(wq, wqh, DMODEL * DMODEL);
    cvt_half<<<(DMODEL * KSTR) / 2048, 256>>>(wk, wkh, DMODEL * KSTR);
    cvt_half<<<(DMODEL * KSTR) / 2048, 256>>>(wv, wvh, DMODEL * KSTR);
    cvt_half<<<(DMODEL * DMODEL) / 2048, 256>>>(wo, woh, DMODEL * DMODEL);

    cudaFuncSetAttribute(gemm_f16,
                         cudaFuncAttributeMaxDynamicSharedMemorySize, GEMM_SMEM);
    cudaFuncSetAttribute(flash_f16,
                         cudaFuncAttributeMaxDynamicSharedMemorySize, FA_SMEM);

    // QKV projections
    gemm_f16<<<dim3(DMODEL / 128, M / 128), 256, GEMM_SMEM>>>(
        xh, wqh, Qp, M, DMODEL, DMODEL);
    gemm_f16<<<dim3(KSTR / 128, M / 128), 256, GEMM_SMEM>>>(
        xh, wkh, Kp, M, KSTR, DMODEL);
    gemm_f16<<<dim3(KSTR / 128, M / 128), 256, GEMM_SMEM>>>(
        xh, wvh, Vp, M, KSTR, DMODEL);

    // RoPE -> fp16 (scale folded into Q); V -> fp16
    const float scale = 0.08838834764831845f;
    rope_half<<<dim3(M, NH), 64>>>(Qp, qbh, NH, scale);
    rope_half<<<dim3(M, NKV), 64>>>(Kp, kbh, NKV, 1.0f);
    cvt_half<<<(M * KSTR) / 2048, 256>>>(Vp, vbh, M * KSTR);

    // Flash attention
    flash_f16<<<dim3(SEQ / 64, NH, BSZ), 128, FA_SMEM>>>(qbh, kbh, vbh, ohp);

    // Output projection
    gemm_f16<<<dim3(DMODEL / 128, M / 128), 256, GEMM_SMEM>>>(
        ohp, woh, out, M, DMODEL, DMODEL);
}

// round 16
// speedup vs baseline: 1.8096x; 1.0265x over previous
#include <cuda_runtime.h>
#include <cuda_fp16.h>
#include <math.h>

#define BSZ 2
#define SEQ 2048
#define DMODEL 4096
#define NH 32
#define NKV 8
#define NREP 4
#define HD 128

#define QSTR (NH * HD)
#define KSTR (NKV * HD)
#define MROWS (BSZ * SEQ)

// ---- fp32 scratch (pre-RoPE Q/K, pre-convert V) ----
__device__ float g_Q[MROWS * QSTR];
__device__ float g_K[MROWS * KSTR];
__device__ float g_V[MROWS * KSTR];

// ---- fp16 buffers ----
__device__ __half g_xh[MROWS * DMODEL];
__device__ __half g_wqh[DMODEL * DMODEL];
__device__ __half g_wkh[DMODEL * KSTR];
__device__ __half g_wvh[DMODEL * KSTR];
__device__ __half g_woh[DMODEL * DMODEL];
__device__ __half g_oh[MROWS * DMODEL];
__device__ __half g_qbh[MROWS * QSTR];
__device__ __half g_kbh[MROWS * KSTR];
__device__ __half g_vbh[MROWS * KSTR];

// ---------------------------------------------------------------------------
// asm helpers
// ---------------------------------------------------------------------------
__device__ __forceinline__ void cp16(unsigned int dst, const void* src)
{
    asm volatile("cp.async.cg.shared.global [%0], [%1], 16;" :: "r"(dst), "l"(src));
}
__device__ __forceinline__ void cp_commit()
{
    asm volatile("cp.async.commit_group;");
}
__device__ __forceinline__ void cp_wait1()
{
    asm volatile("cp.async.wait_group 1;");
}
__device__ __forceinline__ void cp_wait0()
{
    asm volatile("cp.async.wait_group 0;");
}
__device__ __forceinline__ void ldm_x4(unsigned int* r, unsigned int addr)
{
    asm volatile("ldmatrix.sync.aligned.m8n8.x4.shared.b16 {%0,%1,%2,%3}, [%4];"
                 : "=r"(r[0]), "=r"(r[1]), "=r"(r[2]), "=r"(r[3]) : "r"(addr));
}
__device__ __forceinline__ void ldm_x4t(unsigned int* r, unsigned int addr)
{
    asm volatile("ldmatrix.sync.aligned.m8n8.x4.trans.shared.b16 {%0,%1,%2,%3}, [%4];"
                 : "=r"(r[0]), "=r"(r[1]), "=r"(r[2]), "=r"(r[3]) : "r"(addr));
}
__device__ __forceinline__ void mma16816h(float* d, const unsigned int* a,
                                          unsigned int b0, unsigned int b1)
{
    asm volatile(
        "mma.sync.aligned.m16n8k16.row.col.f32.f16.f16.f32 "
        "{%0,%1,%2,%3}, {%4,%5,%6,%7}, {%8,%9}, {%0,%1,%2,%3};"
        : "+f"(d[0]), "+f"(d[1]), "+f"(d[2]), "+f"(d[3])
        : "r"(a[0]), "r"(a[1]), "r"(a[2]), "r"(a[3]), "r"(b0), "r"(b1));
}
__device__ __forceinline__ unsigned int pack_h2(float x, float y)
{
    __half2 t = __floats2half2_rn(x, y);
    return *(unsigned int*)&t;
}

// ---------------------------------------------------------------------------
// fp32 -> fp16. n % 8 == 0.
// ---------------------------------------------------------------------------
__global__ __launch_bounds__(256) void cvt_half(
    const float* __restrict__ in, __half* __restrict__ out, int n)
{
    int i = (blockIdx.x * blockDim.x + threadIdx.x) * 8;
    if (i >= n) {
        return;
    }
    float4 a = *(const float4*)(in + i);
    float4 b = *(const float4*)(in + i + 4);
    uint4 v;
    v.x = pack_h2(a.x, a.y);
    v.y = pack_h2(a.z, a.w);
    v.z = pack_h2(b.x, b.y);
    v.w = pack_h2(b.z, b.w);
    *(uint4*)(out + i) = v;
}

// ---------------------------------------------------------------------------
// Tensor-core GEMM, plain fp16, fp32 accum.
// C[M,N] = A[M,K] @ B[K,N]. 128x128 tile, BK=64, 256 threads, 2-stage.
// M%128==0, N%128==0, K%64==0.
// ---------------------------------------------------------------------------
#define AST 72                                   // 64 k + 8 pad (144B rows)
#define BST 136
#define AS_BYTES (128 * AST * 2)                 // 18432
#define BS_BYTES (64 * BST * 2)                  // 17408
#define STAGE_BYTES (AS_BYTES + BS_BYTES)        // 35840
#define GEMM_SMEM (2 * STAGE_BYTES)              // 71680

__device__ __forceinline__ void issue_stage(
    unsigned int s0,
    const __half* __restrict__ A, const __half* __restrict__ B,
    int K, int N, int bm, int bn, int k0, int tid)
{
    // A: 128 rows x 64 halfs = 1024 chunks of 8 halfs; 4 per thread
#pragma unroll
    for (int u = 0; u < 4; u++) {
        int idx = tid + u * 256;
        int r   = idx >> 3;
        int kc  = (idx & 7) << 3;
        cp16(s0 + (unsigned int)(r * AST + kc) * 2u,
             A + (size_t)(bm + r) * K + k0 + kc);
    }
    // B: 64 rows x 128 halfs = 1024 chunks; 4 per thread
    unsigned int sb = s0 + AS_BYTES;
#pragma unroll
    for (int u = 0; u < 4; u++) {
        int idx = tid + u * 256;
        int r   = idx >> 4;
        int nc  = (idx & 15) << 3;
        cp16(sb + (unsigned int)(r * BST + nc) * 2u,
             B + (size_t)(k0 + r) * N + bn + nc);
    }
}

__global__ __launch_bounds__(256) void gemm_f16(
    const __half* __restrict__ A, const __half* __restrict__ B,
    float* __restrict__ C, int M, int N, int K)
{
    extern __shared__ char smraw[];
    const int tid  = threadIdx.x;
    const int warp = tid >> 5;
    const int lane = tid & 31;
    const int wm   = warp >> 2;
    const int wn   = warp & 3;
    const int bm   = blockIdx.y * 128;
    const int bn   = blockIdx.x * 128;

    unsigned int sbase = (unsigned int)__cvta_generic_to_shared(smraw);

    float acc[4][4][4];
#pragma unroll
    for (int i = 0; i < 4; i++) {
#pragma unroll
        for (int j = 0; j < 4; j++) {
#pragma unroll
            for (int r = 0; r < 4; r++) {
                acc[i][j][r] = 0.0f;
            }
        }
    }

    const int niter = K / 64;
    issue_stage(sbase, A, B, K, N, bm, bn, 0, tid);
    cp_commit();

    const int arow  = lane & 15;
    const int acolh = (lane >> 4) << 3;

    for (int it = 0; it < niter; it++) {
        int cur = it & 1;
        if (it + 1 < niter) {
            issue_stage(sbase + (unsigned int)(cur ^ 1) * STAGE_BYTES,
                        A, B, K, N, bm, bn, (it + 1) * 64, tid);
            cp_commit();
            cp_wait1();
        } else {
            cp_wait0();
        }
        __syncthreads();

        unsigned int s0 = sbase + (unsigned int)cur * STAGE_BYTES;
        unsigned int sB = s0 + AS_BYTES;

#pragma unroll
        for (int ks = 0; ks < 4; ks++) {
            int k16 = ks * 16;
            unsigned int af[4][4];
#pragma unroll
            for (int mi = 0; mi < 4; mi++) {
                unsigned int addr = s0 +
                    (unsigned int)((wm * 64 + mi * 16 + arow) * AST + k16 + acolh) * 2u;
                ldm_x4(af[mi], addr);
            }
            unsigned int bf[2][4];
#pragma unroll
            for (int nj = 0; nj < 2; nj++) {
                unsigned int addr = sB +
                    (unsigned int)((k16 + arow) * BST + wn * 32 + nj * 16 + acolh) * 2u;
                ldm_x4t(bf[nj], addr);
            }
#pragma unroll
            for (int mi = 0; mi < 4; mi++) {
#pragma unroll
                for (int nj = 0; nj < 2; nj++) {
                    mma16816h(acc[mi][2 * nj],     af[mi], bf[nj][0], bf[nj][1]);
                    mma16816h(acc[mi][2 * nj + 1], af[mi], bf[nj][2], bf[nj][3]);
                }
            }
        }
        __syncthreads();
    }

    const int r0 = bm + wm * 64;
    const int c0 = bn + wn * 32;
#pragma unroll
    for (int mi = 0; mi < 4; mi++) {
#pragma unroll
        for (int ng = 0; ng < 4; ng++) {
            int row = r0 + mi * 16 + (lane >> 2);
            int col = c0 + ng * 8 + (lane & 3) * 2;
            *(float2*)(C + (size_t)row * N + col) =
                make_float2(acc[mi][ng][0], acc[mi][ng][1]);
            *(float2*)(C + (size_t)(row + 8) * N + col) =
                make_float2(acc[mi][ng][2], acc[mi][ng][3]);
        }
    }
}

// ---------------------------------------------------------------------------
// RoPE -> fp16 (accurate double trig; scale folded). grid=(rows,nheads),64thr.
// ---------------------------------------------------------------------------
__global__ __launch_bounds__(64) void rope_half(
    const float* __restrict__ x, __half* __restrict__ out, int nheads, float scale)
{
    const int pair = threadIdx.x;
    const int h    = blockIdx.y;
    const int row  = blockIdx.x;
    const int s    = row % SEQ;

    double inv_d = exp(-(double)pair * (1.0 / 64.0) * log(10000.0));
    float  inv_f = (float)inv_d;
    float  ang_f = (float)s * inv_f;

    float c  = (float)cos((double)ang_f);
    float sn = (float)sin((double)ang_f);

    size_t off = (size_t)row * (nheads * HD) + h * HD + pair * 2;
    float x0 = x[off];
    float x1 = x[off + 1];
    float r0 = (x0 * c - x1 * sn) * scale;
    float r1 = (x0 * sn + x1 * c) * scale;

    *(unsigned int*)(out + off) = pack_h2(r0, r1);
}

// ---------------------------------------------------------------------------
// Flash attention (fp16 mma, fp32 softmax/accum). Writes fp16 O.
// Block = (128-row q tile, head, batch). 8 warps (16 rows each).
// K-tiles of 32 keys, 2-stage cp.async.
// ---------------------------------------------------------------------------
#define FST 136
#define FQ_BYTES (128 * FST * 2)          // 34816
#define FK_BYTES (32 * FST * 2)           // 8704
#define FSTAGE (2 * FK_BYTES)             // K, V
#define FA_SMEM (FQ_BYTES + 2 * FSTAGE)   // 69632

__global__ __launch_bounds__(256) void flash_f16(
    const __half* __restrict__ Qh, const __half* __restrict__ Kh,
    const __half* __restrict__ Vh, __half* __restrict__ O)
{
    extern __shared__ char smraw[];
    const int tid  = threadIdx.x;
    const int warp = tid >> 5;       // 0..7
    const int lane = tid & 31;
    const int qt   = blockIdx.x;
    const int h    = blockIdx.y;
    const int b    = blockIdx.z;
    const int g    = h >> 2;
    const int q0   = qt * 128;

    unsigned int sbase = (unsigned int)__cvta_generic_to_shared(smraw);
    unsigned int sQ    = sbase;
    unsigned int sKV   = sbase + FQ_BYTES;

    {
        size_t rowb = (size_t)b * SEQ + q0;
        for (int i = tid; i < 2048; i += 256) {
            int r = i >> 4;
            int c = (i & 15) << 3;
            size_t goff = (rowb + r) * QSTR + h * HD + c;
            cp16(sQ + (unsigned int)(r * FST + c) * 2u, Qh + goff);
        }
    }
    const int nkt = 4 * qt + 4;
    {
        size_t rowb = (size_t)b * SEQ;
        for (int i = tid; i < 512; i += 256) {
            int r = i >> 4;
            int c = (i & 15) << 3;
            size_t goff = (rowb + r) * KSTR + g * HD + c;
            unsigned int d = sKV + (unsigned int)(r * FST + c) * 2u;
            cp16(d, Kh + goff);
            cp16(d + FK_BYTES, Vh + goff);
        }
    }
    cp_commit();

    float oacc[16][4];
#pragma unroll
    for (int i = 0; i < 16; i++) {
#pragma unroll
        for (int j = 0; j < 4; j++) {
            oacc[i][j] = 0.0f;
        }
    }
    float sm0 = -INFINITY;
    float sm1 = -INFINITY;
    float sl0 = 0.0f;
    float sl1 = 0.0f;

    const int arow  = lane & 15;
    const int acolh = (lane >> 4) << 3;
    const int brow  = (lane & 7) | ((lane >> 1) & 8);
    const int bcolh = ((lane >> 3) & 1) << 3;

    for (int kt = 0; kt < nkt; kt++) {
        int st = kt & 1;
        if (kt + 1 < nkt) {
            size_t rowb = (size_t)b * SEQ + (kt + 1) * 32;
            unsigned int sN = sKV + (unsigned int)(st ^ 1) * FSTAGE;
            for (int i = tid; i < 512; i += 256) {
                int r = i >> 4;
                int c = (i & 15) << 3;
                size_t goff = (rowb + r) * KSTR + g * HD + c;
                unsigned int d = sN + (unsigned int)(r * FST + c) * 2u;
                cp16(d, Kh + goff);
                cp16(d + FK_BYTES, Vh + goff);
            }
            cp_commit();
            cp_wait1();
        } else {
            cp_wait0();
        }
        __syncthreads();

        unsigned int pK = sKV + (unsigned int)st * FSTAGE;
        unsigned int pV = pK + FK_BYTES;

        float sacc[4][4];
#pragma unroll
        for (int i = 0; i < 4; i++) {
#pragma unroll
            for (int j = 0; j < 4; j++) {
                sacc[i][j] = 0.0f;
            }
        }
#pragma unroll
        for (int kk = 0; kk < 8; kk++) {
            unsigned int af[4];
            unsigned int aaddr = sQ +
                (unsigned int)((warp * 16 + arow) * FST + kk * 16 + acolh) * 2u;
            ldm_x4(af, aaddr);
#pragma unroll
            for (int ng = 0; ng < 2; ng++) {
                unsigned int bf[4];
                unsigned int baddr = pK +
                    (unsigned int)((ng * 16 + brow) * FST + kk * 16 + bcolh) * 2u;
                ldm_x4(bf, baddr);
                mma16816h(sacc[2 * ng],     af, bf[0], bf[1]);
                mma16816h(sacc[2 * ng + 1], af, bf[2], bf[3]);
            }
        }

        int k0 = kt * 32;
        if (kt >= 4 * qt) {
#pragma unroll
            for (int nt = 0; nt < 4; nt++) {
#pragma unroll
                for (int c = 0; c < 4; c++) {
                    int kg = k0 + nt * 8 + ((lane & 3) << 1) + (c & 1);
                    int qg = q0 + warp * 16 + (lane >> 2) + ((c >> 1) << 3);
                    if (kg > qg) {
                        sacc[nt][c] = -INFINITY;
                    }
                }
            }
        }

        float tm0 = -INFINITY;
        float tm1 = -INFINITY;
#pragma unroll
        for (int nt = 0; nt < 4; nt++) {
            tm0 = fmaxf(tm0, fmaxf(sacc[nt][0], sacc[nt][1]));
            tm1 = fmaxf(tm1, fmaxf(sacc[nt][2], sacc[nt][3]));
        }
        tm0 = fmaxf(tm0, __shfl_xor_sync(0xFFFFFFFFu, tm0, 1));
        tm0 = fmaxf(tm0, __shfl_xor_sync(0xFFFFFFFFu, tm0, 2));
        tm1 = fmaxf(tm1, __shfl_xor_sync(0xFFFFFFFFu, tm1, 1));
        tm1 = fmaxf(tm1, __shfl_xor_sync(0xFFFFFFFFu, tm1, 2));

        float mn0 = fmaxf(sm0, tm0);
        float mn1 = fmaxf(sm1, tm1);
        float al0 = expf(sm0 - mn0);
        float al1 = expf(sm1 - mn1);
        sm0 = mn0;
        sm1 = mn1;

        float rs0 = 0.0f;
        float rs1 = 0.0f;
#pragma unroll
        for (int nt = 0; nt < 4; nt++) {
            float p0 = expf(sacc[nt][0] - mn0);
            float p1 = expf(sacc[nt][1] - mn0);
            float p2 = expf(sacc[nt][2] - mn1);
            float p3 = expf(sacc[nt][3] - mn1);
            sacc[nt][0] = p0;
            sacc[nt][1] = p1;
            sacc[nt][2] = p2;
            sacc[nt][3] = p3;
            rs0 += p0 + p1;
            rs1 += p2 + p3;
        }
        rs0 += __shfl_xor_sync(0xFFFFFFFFu, rs0, 1);
        rs0 += __shfl_xor_sync(0xFFFFFFFFu, rs0, 2);
        rs1 += __shfl_xor_sync(0xFFFFFFFFu, rs1, 1);
        rs1 += __shfl_xor_sync(0xFFFFFFFFu, rs1, 2);
        sl0 = sl0 * al0 + rs0;
        sl1 = sl1 * al1 + rs1;

#pragma unroll
        for (int nt = 0; nt < 16; nt++) {
            oacc[nt][0] *= al0;
            oacc[nt][1] *= al0;
            oacc[nt][2] *= al1;
            oacc[nt][3] *= al1;
        }

#pragma unroll
        for (int ks = 0; ks < 2; ks++) {
            int ntA = 2 * ks;
            int ntB = 2 * ks + 1;
            unsigned int ap[4];
            ap[0] = pack_h2(sacc[ntA][0], sacc[ntA][1]);
            ap[1] = pack_h2(sacc[ntA][2], sacc[ntA][3]);
            ap[2] = pack_h2(sacc[ntB][0], sacc[ntB][1]);
            ap[3] = pack_h2(sacc[ntB][2], sacc[ntB][3]);
#pragma unroll
            for (int nt2 = 0; nt2 < 8; nt2++) {
                unsigned int bf[4];
                unsigned int baddr = pV +
                    (unsigned int)((ks * 16 + arow) * FST + nt2 * 16 + acolh) * 2u;
                ldm_x4t(bf, baddr);
                mma16816h(oacc[2 * nt2],     ap, bf[0], bf[1]);
                mma16816h(oacc[2 * nt2 + 1], ap, bf[2], bf[3]);
            }
        }
        __syncthreads();
    }

    float i0 = 1.0f / sl0;
    float i1 = 1.0f / sl1;
    int rg = q0 + warp * 16 + (lane >> 2);
    size_t orow0 = ((size_t)b * SEQ + rg) * QSTR + h * HD;
    size_t orow1 = orow0 + (size_t)8 * QSTR;
#pragma unroll
    for (int nt = 0; nt < 16; nt++) {
        int col = nt * 8 + ((lane & 3) << 1);
        *(unsigned int*)(O + orow0 + col) = pack_h2(oacc[nt][0] * i0, oacc[nt][1] * i0);
        *(unsigned int*)(O + orow1 + col) = pack_h2(oacc[nt][2] * i1, oacc[nt][3] * i1);
    }
}

// ---------------------------------------------------------------------------
extern "C" void kernel_launch(void* const* d_in, const int* in_sizes, int n_in,
                              void* d_out, int out_size)
{
    const float* x;
    const float* wq;
    const float* wk;
    const float* wv;
    const float* wo;
    if (n_in >= 7 && in_sizes[0] == 1 && in_sizes[1] == 1) {
        if (in_sizes[2] == 16777216) {
            x  = (const float*)d_in[2];
            wq = (const float*)d_in[3];
            wk = (const float*)d_in[4];
            wv = (const float*)d_in[5];
            wo = (const float*)d_in[6];
        } else {
            wk = (const float*)d_in[2];
            wo = (const float*)d_in[3];
            wq = (const float*)d_in[4];
            wv = (const float*)d_in[5];
            x  = (const float*)d_in[6];
        }
    } else {
        x  = (const float*)d_in[0];
        wq = (const float*)d_in[1];
        wk = (const float*)d_in[2];
        wv = (const float*)d_in[3];
        wo = (const float*)d_in[4];
    }
    float* out = (float*)d_out;

    float* Qp;
    float* Kp;
    float* Vp;
    cudaGetSymbolAddress((void**)&Qp, g_Q);
    cudaGetSymbolAddress((void**)&Kp, g_K);
    cudaGetSymbolAddress((void**)&Vp, g_V);

    __half* xh;
    __half* wqh;
    __half* wkh;
    __half* wvh;
    __half* woh;
    __half* ohp;
    __half* qbh;
    __half* kbh;
    __half* vbh;
    cudaGetSymbolAddress((void**)&xh,  g_xh);
    cudaGetSymbolAddress((void**)&wqh, g_wqh);
    cudaGetSymbolAddress((void**)&wkh, g_wkh);
    cudaGetSymbolAddress((void**)&wvh, g_wvh);
    cudaGetSymbolAddress((void**)&woh, g_woh);
    cudaGetSymbolAddress((void**)&ohp, g_oh);
    cudaGetSymbolAddress((void**)&qbh, g_qbh);
    cudaGetSymbolAddress((void**)&kbh, g_kbh);
    cudaGetSymbolAddress((void**)&vbh, g_vbh);

    const int M = MROWS;

    // fp32 -> fp16 converts
    cvt_half<<<(M * DMODEL) / 2048, 256>>>(x, xh, M * DMODEL);
    cvt_half<<<(DMODEL * DMODEL) / 2048, 256>>>(wq, wqh, DMODEL * DMODEL);
    cvt_half<<<(DMODEL * KSTR) / 2048, 256>>>(wk, wkh, DMODEL * KSTR);
    cvt_half<<<(DMODEL * KSTR) / 2048, 256>>>(wv, wvh, DMODEL * KSTR);
    cvt_half<<<(DMODEL * DMODEL) / 2048, 256>>>(wo, woh, DMODEL * DMODEL);

    cudaFuncSetAttribute(gemm_f16,
                         cudaFuncAttributeMaxDynamicSharedMemorySize, GEMM_SMEM);
    cudaFuncSetAttribute(flash_f16,
                         cudaFuncAttributeMaxDynamicSharedMemorySize, FA_SMEM);

    // QKV projections
    gemm_f16<<<dim3(DMODEL / 128, M / 128), 256, GEMM_SMEM>>>(
        xh, wqh, Qp, M, DMODEL, DMODEL);
    gemm_f16<<<dim3(KSTR / 128, M / 128), 256, GEMM_SMEM>>>(
        xh, wkh, Kp, M, KSTR, DMODEL);
    gemm_f16<<<dim3(KSTR / 128, M / 128), 256, GEMM_SMEM>>>(
        xh, wvh, Vp, M, KSTR, DMODEL);

    // RoPE -> fp16 (scale folded into Q); V -> fp16
    const float scale = 0.08838834764831845f;
    rope_half<<<dim3(M, NH), 64>>>(Qp, qbh, NH, scale);
    rope_half<<<dim3(M, NKV), 64>>>(Kp, kbh, NKV, 1.0f);
    cvt_half<<<(M * KSTR) / 2048, 256>>>(Vp, vbh, M * KSTR);

    // Flash attention (128-row q tiles)
    flash_f16<<<dim3(SEQ / 128, NH, BSZ), 256, FA_SMEM>>>(qbh, kbh, vbh, ohp);

    // Output projection
    gemm_f16<<<dim3(DMODEL / 128, M / 128), 256, GEMM_SMEM>>>(
        ohp, woh, out, M, DMODEL, DMODEL);
}